// round 6
// baseline (speedup 1.0000x reference)
#include <cuda_runtime.h>
#include <math.h>
#include <stdint.h>

// Problem constants (fixed by the reference)
#define NB 4
#define LQ 5440
#define LV 5440
#define CD 256
#define NH 8
#define HD 32
#define MROWS (NB * LQ)   // 21760
#define NFUSE 384
#define MTILES (MROWS / 128)  // 170

// Scratch (device globals: no allocation allowed in kernel_launch)
__device__ float g_vproj  [(size_t)MROWS * CD];
__device__ float g_offattn[(size_t)MROWS * NFUSE];
__device__ float g_acc    [(size_t)MROWS * CD];
__device__ float g_bf     [NFUSE];
// Weights pre-packed in mma-fragment order, tf32-converted:
// [nt][stage(16)][2048 words]; word = ((tn*2+tk)*32 + lane)*2 + reg
__device__ uint32_t g_BpV[2 * 16 * 2048];
__device__ uint32_t g_BpF[3 * 16 * 2048];
__device__ uint32_t g_BpO[2 * 16 * 2048];

// ---------------------------------------------------------------------------
__device__ __forceinline__ unsigned f2tf(float f) {
    unsigned r;
    asm("cvt.rna.tf32.f32 %0, %1;" : "=r"(r) : "f"(f));
    return r;
}

__device__ __forceinline__ void mma_tf32(float* c, const unsigned* a, const unsigned* b) {
    asm volatile(
        "mma.sync.aligned.m16n8k8.row.col.f32.tf32.tf32.f32 "
        "{%0,%1,%2,%3}, {%4,%5,%6,%7}, {%8,%9}, {%0,%1,%2,%3};"
        : "+f"(c[0]), "+f"(c[1]), "+f"(c[2]), "+f"(c[3])
        : "r"(a[0]), "r"(a[1]), "r"(a[2]), "r"(a[3]), "r"(b[0]), "r"(b[1]));
}

// ---------------------------------------------------------------------------
// Weight pre-pack into fragment order (tf32 bits) + bias pack.
// Per target: nt tiles of [K=256, n=128]. word w in stage s:
//   t = w>>6 (tn = t>>1, tk = t&1), lane = (w>>1)&31, reg = w&1
//   n = tn*8 + (lane>>2);  k = s*16 + tk*8 + (lane&3) + 4*reg
// ---------------------------------------------------------------------------
__global__ void pack_B(const float* __restrict__ W_off, const float* __restrict__ b_off,
                       const float* __restrict__ W_at,  const float* __restrict__ b_at,
                       const float* __restrict__ W_val, const float* __restrict__ W_out)
{
    const int i = blockIdx.x * 256 + threadIdx.x;
    if (i < NFUSE) g_bf[i] = (i < 256) ? b_off[i] : b_at[i - 256];
    if (i >= 229376) return;

    uint32_t* dst;
    int idx, which;                 // 0=V, 1=F, 2=O
    if (i < 65536)       { dst = g_BpV; idx = i;          which = 0; }
    else if (i < 163840) { dst = g_BpF; idx = i - 65536;  which = 1; }
    else                 { dst = g_BpO; idx = i - 163840; which = 2; }

    const int nt   = idx >> 15;
    const int rem  = idx & 32767;
    const int s    = rem >> 11;
    const int w    = rem & 2047;
    const int t    = w >> 6;
    const int lane = (w >> 1) & 31;
    const int reg  = w & 1;

    const int n  = (t >> 1) * 8 + (lane >> 2);
    const int k  = s * 16 + (t & 1) * 8 + (lane & 3) + 4 * reg;
    const int ng = nt * 128 + n;

    float v;
    if (which == 0)      v = W_val[k * 256 + ng];
    else if (which == 2) v = W_out[k * 256 + ng];
    else                 v = (ng < 256) ? W_off[k * 256 + ng] : W_at[k * 128 + (ng - 256)];

    dst[idx] = f2tf(v);
}

// ---------------------------------------------------------------------------
// tf32 mma.sync GEMM with fragment-layout smem.
// Block tile 128x128, BK=16, double-buffered, 8 warps of 64x32.
// Two jobs per launch: blockIdx.x < nt0 -> job 0, else job 1.
// A smem word: ((tm*2+tk)*32 + lane)*4 + reg  (LDS.128 frag loads)
// B smem word: ((tn*2+tk)*32 + lane)*2 + reg  (LDS.64  frag loads)
// ---------------------------------------------------------------------------
__global__ __launch_bounds__(256) void gemm_tf32(
    const float* __restrict__ A0, const uint32_t* __restrict__ B0,
    const float* __restrict__ bias0, float* __restrict__ C0, int N0, int nt0,
    const float* __restrict__ A1, const uint32_t* __restrict__ B1,
    const float* __restrict__ bias1, float* __restrict__ C1, int N1)
{
    __shared__ __align__(16) uint32_t As[2][2048];
    __shared__ __align__(16) uint32_t Bs[2][2048];

    const int tid  = threadIdx.x;
    const int lane = tid & 31;
    const int warp = tid >> 5;
    const int mt   = blockIdx.y;

    const float* A; const uint32_t* Bp; const float* bias; float* C; int N; int nt;
    if ((int)blockIdx.x < nt0) {
        A = A0; Bp = B0; bias = bias0; C = C0; N = N0; nt = blockIdx.x;
    } else {
        A = A1; Bp = B1; bias = bias1; C = C1; N = N1; nt = blockIdx.x - nt0;
    }

    const int wm = (warp >> 2) * 64;
    const int wn = (warp & 3) * 32;

    // A loader mapping: 2 float4 per thread per stage
    const int am  = tid >> 2;           // 0..63 (+64)
    const int akq = (tid & 3) * 4;      // 0,4,8,12
    const int atk = akq >> 3;
    const int areg = ((akq >> 2) & 1) * 2;   // + ((m>>3)&1)

    const float* Abase = A + (size_t)(mt * 128) * 256;
    const uint32_t* Bbase = Bp + (size_t)nt * 16 * 2048;

    float4 la[2];
    uint4  lb[2];
    float acc[4][4][4] = {};

    auto stage_store = [&](int buf) {
#pragma unroll
        for (int i = 0; i < 2; i++) {
            const int m = am + i * 64;
            const int base = ((m >> 4) * 2 + atk) * 128 + (m & 7) * 16 + areg + ((m >> 3) & 1);
            uint32_t* dst = &As[buf][base];
            dst[0]  = f2tf(la[i].x);
            dst[4]  = f2tf(la[i].y);
            dst[8]  = f2tf(la[i].z);
            dst[12] = f2tf(la[i].w);
        }
        *(uint4*)&Bs[buf][tid * 8]     = lb[0];
        *(uint4*)&Bs[buf][tid * 8 + 4] = lb[1];
    };

    // prologue: stage 0
#pragma unroll
    for (int i = 0; i < 2; i++)
        la[i] = *(const float4*)(Abase + (size_t)(am + i * 64) * 256 + akq);
    lb[0] = *(const uint4*)(Bbase + tid * 8);
    lb[1] = *(const uint4*)(Bbase + tid * 8 + 4);
    stage_store(0);
    __syncthreads();

#pragma unroll 1
    for (int s = 0; s < 16; s++) {
        const int buf = s & 1;
        if (s + 1 < 16) {
            const int k0 = (s + 1) * 16;
#pragma unroll
            for (int i = 0; i < 2; i++)
                la[i] = *(const float4*)(Abase + (size_t)(am + i * 64) * 256 + k0 + akq);
            const uint32_t* bsrc = Bbase + (size_t)(s + 1) * 2048;
            lb[0] = *(const uint4*)(bsrc + tid * 8);
            lb[1] = *(const uint4*)(bsrc + tid * 8 + 4);
        }

#pragma unroll
        for (int tk = 0; tk < 2; tk++) {
            unsigned af[4][4], bf[4][2];
#pragma unroll
            for (int mi = 0; mi < 4; mi++) {
                const int tm = (wm >> 4) + mi;
                const uint4 av = *(const uint4*)&As[buf][((tm * 2 + tk) * 32 + lane) * 4];
                af[mi][0] = av.x; af[mi][1] = av.y; af[mi][2] = av.z; af[mi][3] = av.w;
            }
#pragma unroll
            for (int ni = 0; ni < 4; ni++) {
                const int tn = (wn >> 3) + ni;
                const uint2 bv = *(const uint2*)&Bs[buf][((tn * 2 + tk) * 32 + lane) * 2];
                bf[ni][0] = bv.x; bf[ni][1] = bv.y;
            }
#pragma unroll
            for (int mi = 0; mi < 4; mi++)
#pragma unroll
                for (int ni = 0; ni < 4; ni++)
                    mma_tf32(acc[mi][ni], af[mi], bf[ni]);
        }

        if (s + 1 < 16) {
            stage_store((s + 1) & 1);
            __syncthreads();
        }
    }

    // epilogue: bias add + float2 stores
#pragma unroll
    for (int mi = 0; mi < 4; mi++) {
        const int r = mt * 128 + wm + mi * 16 + (lane >> 2);
#pragma unroll
        for (int ni = 0; ni < 4; ni++) {
            const int c = nt * 128 + wn + ni * 8 + (lane & 3) * 2;
            const float2 bv = *(const float2*)&bias[c];
            float2 o0, o1;
            o0.x = acc[mi][ni][0] + bv.x;
            o0.y = acc[mi][ni][1] + bv.y;
            o1.x = acc[mi][ni][2] + bv.x;
            o1.y = acc[mi][ni][3] + bv.y;
            *(float2*)&C[(size_t)r * N + c]       = o0;
            *(float2*)&C[(size_t)(r + 8) * N + c] = o1;
        }
    }
}

// ---------------------------------------------------------------------------
// Deformable sampling — warp-autonomous (unchanged from round 4).
// ---------------------------------------------------------------------------
__global__ __launch_bounds__(256) void ms_sample_kernel(
    const float* __restrict__ refp)   // [B, Lq, 4, 2]
{
    const int q  = blockIdx.x;
    const int b  = blockIdx.y;
    const int bq = b * LQ + q;
    const int t  = threadIdx.x;
    const int h  = t >> 5;
    const int lid = t & 31;

    __shared__ int2 s_tap[NH][64];

    {
        const int lp = lid;
        const float* ap = g_offattn + (size_t)bq * NFUSE + 256 + h * 16;
        float logit = (lid < 16) ? ap[lp] : -1e30f;
        float m = logit;
#pragma unroll
        for (int o = 8; o; o >>= 1) m = fmaxf(m, __shfl_xor_sync(0xFFFFFFFFu, m, o));
        float e = (lid < 16) ? __expf(logit - m) : 0.0f;
        float ssum = e;
#pragma unroll
        for (int o = 8; o; o >>= 1) ssum += __shfl_xor_sync(0xFFFFFFFFu, ssum, o);

        if (lid < 16) {
            const float aw = e / ssum;
            const int l = lp >> 2;
            const int W = 64 >> l;
            const int start = (l == 0) ? 0 : (l == 1) ? 4096 : (l == 2) ? 5120 : 5376;

            const float rx = refp[((size_t)bq * 4 + l) * 2 + 0];
            const float ry = refp[((size_t)bq * 4 + l) * 2 + 1];
            const float* op = g_offattn + (size_t)bq * NFUSE + h * 32 + lp * 2;

            const float x = fmaf(rx, (float)W, op[0]) - 0.5f;
            const float y = fmaf(ry, (float)W, op[1]) - 0.5f;
            const float x0f = floorf(x), y0f = floorf(y);
            const int x0 = (int)x0f, y0 = (int)y0f;
            const float wx = x - x0f, wy = y - y0f;

            const bool xi0 = (x0 >= 0) && (x0 < W);
            const bool xi1 = (x0 + 1 >= 0) && (x0 + 1 < W);
            const bool yi0 = (y0 >= 0) && (y0 < W);
            const bool yi1 = (y0 + 1 >= 0) && (y0 + 1 < W);

            const int i00 = start + y0 * W + x0;
            int2* tp = &s_tap[h][lp * 4];
            bool v;
            v = xi0 && yi0;
            tp[0] = make_int2(v ? i00 : 0,         __float_as_int(v ? aw * (1.f - wx) * (1.f - wy) : 0.f));
            v = xi1 && yi0;
            tp[1] = make_int2(v ? i00 + 1 : 0,     __float_as_int(v ? aw * wx * (1.f - wy) : 0.f));
            v = xi0 && yi1;
            tp[2] = make_int2(v ? i00 + W : 0,     __float_as_int(v ? aw * (1.f - wx) * wy : 0.f));
            v = xi1 && yi1;
            tp[3] = make_int2(v ? i00 + W + 1 : 0, __float_as_int(v ? aw * wx * wy : 0.f));
        }
    }
    __syncwarp();

    const int sub = lid >> 3;
    const int c4  = (lid & 7) * 4;
    const float* vb4 = g_vproj + (size_t)b * LV * CD + h * HD + c4;
    const int2* taps = &s_tap[h][0];

    float ax = 0.f, ay = 0.f, az = 0.f, aw_ = 0.f;
#pragma unroll
    for (int j = 0; j < 16; j++) {
        const int2 tv = taps[j * 4 + sub];
        const float w = __int_as_float(tv.y);
        const float4 v = *(const float4*)(vb4 + (size_t)tv.x * CD);
        ax  = fmaf(w, v.x, ax);
        ay  = fmaf(w, v.y, ay);
        az  = fmaf(w, v.z, az);
        aw_ = fmaf(w, v.w, aw_);
    }
#pragma unroll
    for (int o = 8; o <= 16; o <<= 1) {
        ax  += __shfl_xor_sync(0xFFFFFFFFu, ax,  o);
        ay  += __shfl_xor_sync(0xFFFFFFFFu, ay,  o);
        az  += __shfl_xor_sync(0xFFFFFFFFu, az,  o);
        aw_ += __shfl_xor_sync(0xFFFFFFFFu, aw_, o);
    }
    if (lid < 8) {
        float4 o4 = make_float4(ax, ay, az, aw_);
        *(float4*)&g_acc[(size_t)bq * CD + h * HD + lid * 4] = o4;
    }
}

// ---------------------------------------------------------------------------
// kernel_launch
// Inputs: query, reference_points, value, W_off, b_off, W_attn, b_attn,
//         W_val, b_val, W_out, b_out
// ---------------------------------------------------------------------------
extern "C" void kernel_launch(void* const* d_in, const int* in_sizes, int n_in,
                              void* d_out, int out_size)
{
    const float* query = (const float*)d_in[0];
    const float* refp  = (const float*)d_in[1];
    const float* value = (const float*)d_in[2];
    const float* W_off = (const float*)d_in[3];
    const float* b_off = (const float*)d_in[4];
    const float* W_at  = (const float*)d_in[5];
    const float* b_at  = (const float*)d_in[6];
    const float* W_val = (const float*)d_in[7];
    const float* b_val = (const float*)d_in[8];
    const float* W_out = (const float*)d_in[9];
    const float* b_out = (const float*)d_in[10];
    float* out = (float*)d_out;

    float *vproj, *offattn, *accb, *bf;
    uint32_t *bpv, *bpf, *bpo;
    cudaGetSymbolAddress((void**)&vproj,   g_vproj);
    cudaGetSymbolAddress((void**)&offattn, g_offattn);
    cudaGetSymbolAddress((void**)&accb,    g_acc);
    cudaGetSymbolAddress((void**)&bf,      g_bf);
    cudaGetSymbolAddress((void**)&bpv,     g_BpV);
    cudaGetSymbolAddress((void**)&bpf,     g_BpF);
    cudaGetSymbolAddress((void**)&bpo,     g_BpO);

    dim3 blk(256);

    pack_B<<<897, blk>>>(W_off, b_off, W_at, b_at, W_val, W_out);
    // fused: V-proj (2 n-tiles) + offattn-proj (3 n-tiles) in one launch
    gemm_tf32<<<dim3(5, MTILES), blk>>>(value, bpv, b_val, vproj, 256, 2,
                                        query, bpf, bf, offattn, NFUSE);
    ms_sample_kernel<<<dim3(LQ, NB), blk>>>(refp);
    gemm_tf32<<<dim3(2, MTILES), blk>>>(accb, bpo, b_out, out, 256, 2,
                                        accb, bpo, b_out, out, 256);
}

// round 7
// speedup vs baseline: 1.3678x; 1.3678x over previous
#include <cuda_runtime.h>
#include <cuda_fp16.h>
#include <math.h>
#include <stdint.h>

// Problem constants (fixed by the reference)
#define NB 4
#define LQ 5440
#define LV 5440
#define CD 256
#define NH 8
#define HD 32
#define MROWS (NB * LQ)   // 21760
#define NFUSE 384
#define MTILES (MROWS / 128)  // 170

// Scratch (device globals: no allocation allowed in kernel_launch)
__device__ float  g_vproj  [(size_t)MROWS * CD];     // V-proj output (fp32, sampler gathers)
__device__ float  g_offattn[(size_t)MROWS * NFUSE];  // fused proj output (fp32)
__device__ __half g_qH  [(size_t)MROWS * CD];        // query in fp16
__device__ __half g_vH  [(size_t)MROWS * CD];        // value in fp16
__device__ __half g_accH[(size_t)MROWS * CD];        // sampler output in fp16
__device__ float  g_bf  [NFUSE];
// Weights pre-packed as fp16x2 words in m16n8k16 B-fragment order:
// [nt][stage(8)][2048 words]; word w: t=w>>6 (tn=t>>1,tk=t&1), lane=(w>>1)&31, reg=w&1
__device__ uint32_t g_BpV[2 * 8 * 2048];
__device__ uint32_t g_BpF[3 * 8 * 2048];
__device__ uint32_t g_BpO[2 * 8 * 2048];

// ---------------------------------------------------------------------------
__device__ __forceinline__ uint32_t smem_u32(const void* p) {
    uint32_t a;
    asm("{ .reg .u64 t; cvta.to.shared.u64 t, %1; cvt.u32.u64 %0, t; }" : "=r"(a) : "l"(p));
    return a;
}

__device__ __forceinline__ void cp_async16(uint32_t dst, const void* src) {
    asm volatile("cp.async.cg.shared.global [%0], [%1], 16;" :: "r"(dst), "l"(src) : "memory");
}

#define CP_COMMIT() asm volatile("cp.async.commit_group;" ::: "memory")

#define LDSM_X4(r, a) \
    asm volatile("ldmatrix.sync.aligned.m8n8.x4.shared.b16 {%0,%1,%2,%3}, [%4];" \
        : "=r"((r)[0]), "=r"((r)[1]), "=r"((r)[2]), "=r"((r)[3]) : "r"(a))

__device__ __forceinline__ void mma_f16(float* c, const unsigned* a, const unsigned* b) {
    asm volatile(
        "mma.sync.aligned.m16n8k16.row.col.f32.f16.f16.f32 "
        "{%0,%1,%2,%3}, {%4,%5,%6,%7}, {%8,%9}, {%0,%1,%2,%3};"
        : "+f"(c[0]), "+f"(c[1]), "+f"(c[2]), "+f"(c[3])
        : "r"(a[0]), "r"(a[1]), "r"(a[2]), "r"(a[3]), "r"(b[0]), "r"(b[1]));
}

// ---------------------------------------------------------------------------
// Convert query & value fp32 -> fp16 (float4 -> 2x half2 per thread)
// ---------------------------------------------------------------------------
__global__ void convert_h(const float4* __restrict__ q, const float4* __restrict__ v)
{
    const int i = blockIdx.x * 256 + threadIdx.x;   // 0 .. 2*1392640-1
    const float4* src;
    __half* dst;
    int idx;
    if (i < MROWS * 64) { src = q; dst = g_qH; idx = i; }
    else                { src = v; dst = g_vH; idx = i - MROWS * 64; }
    const float4 f = src[idx];
    __half2 a = __floats2half2_rn(f.x, f.y);
    __half2 b = __floats2half2_rn(f.z, f.w);
    uint2 o;
    o.x = *(uint32_t*)&a;
    o.y = *(uint32_t*)&b;
    *(uint2*)&dst[(size_t)idx * 4] = o;
}

// ---------------------------------------------------------------------------
// Weight pre-pack into m16n8k16 B-fragment order (fp16x2 words) + bias pack.
// word: n = nt*128 + tn*8 + (lane>>2), k = s*32 + tk*16 + (lane&3)*2 + 8*reg,
// holds halves (k, k+1).
// ---------------------------------------------------------------------------
__global__ void pack_B(const float* __restrict__ W_off, const float* __restrict__ b_off,
                       const float* __restrict__ W_at,  const float* __restrict__ b_at,
                       const float* __restrict__ W_val, const float* __restrict__ W_out)
{
    const int i = blockIdx.x * 256 + threadIdx.x;
    if (i < NFUSE) g_bf[i] = (i < 256) ? b_off[i] : b_at[i - 256];
    if (i >= 114688) return;   // 32768 V + 49152 F + 32768 O words

    uint32_t* dst;
    int idx, which;                 // 0=V, 1=F, 2=O
    if (i < 32768)      { dst = g_BpV; idx = i;         which = 0; }
    else if (i < 81920) { dst = g_BpF; idx = i - 32768; which = 1; }
    else                { dst = g_BpO; idx = i - 81920; which = 2; }

    const int nt   = idx >> 14;
    const int rem  = idx & 16383;
    const int s    = rem >> 11;
    const int w    = rem & 2047;
    const int t    = w >> 6;
    const int lane = (w >> 1) & 31;
    const int reg  = w & 1;

    const int n  = (t >> 1) * 8 + (lane >> 2);
    const int k  = s * 32 + (t & 1) * 16 + (lane & 3) * 2 + 8 * reg;
    const int ng = nt * 128 + n;

    float v0, v1;
    if (which == 0)      { v0 = W_val[k * 256 + ng]; v1 = W_val[(k + 1) * 256 + ng]; }
    else if (which == 2) { v0 = W_out[k * 256 + ng]; v1 = W_out[(k + 1) * 256 + ng]; }
    else if (ng < 256)   { v0 = W_off[k * 256 + ng]; v1 = W_off[(k + 1) * 256 + ng]; }
    else                 { v0 = W_at[k * 128 + ng - 256]; v1 = W_at[(k + 1) * 128 + ng - 256]; }

    __half2 hv = __floats2half2_rn(v0, v1);
    dst[idx] = *(uint32_t*)&hv;
}

// ---------------------------------------------------------------------------
// fp16 mma.sync GEMM: C[M,N] = A[M,256] @ W + bias. A fp16 row-major global,
// B pre-packed fragment order. Block tile 128x128, BK=32, 3-stage cp.async
// pipeline, ldmatrix.x4 A frags from XOR-swizzled smem, LDS.64 B frags.
// Two jobs per launch (blockIdx.x < nt0 -> job 0).
// ---------------------------------------------------------------------------
__global__ __launch_bounds__(256, 2) void gemm_f16(
    const __half* __restrict__ A0, const uint32_t* __restrict__ B0,
    const float* __restrict__ bias0, float* __restrict__ C0, int N0, int nt0,
    const __half* __restrict__ A1, const uint32_t* __restrict__ B1,
    const float* __restrict__ bias1, float* __restrict__ C1, int N1)
{
    __shared__ __align__(16) uint8_t sm[3][16384];   // per stage: A 8KB | B 8KB

    const int tid  = threadIdx.x;
    const int lane = tid & 31;
    const int warp = tid >> 5;
    const int mt   = blockIdx.y;

    const __half* A; const uint32_t* Bp; const float* bias; float* C; int N; int nt;
    if ((int)blockIdx.x < nt0) {
        A = A0; Bp = B0; bias = bias0; C = C0; N = N0; nt = blockIdx.x;
    } else {
        A = A1; Bp = B1; bias = bias1; C = C1; N = N1; nt = blockIdx.x - nt0;
    }

    const int wm = (warp >> 2) * 64;
    const int wn = (warp & 3) * 32;

    const uint32_t smb = smem_u32(sm);
    const __half* Abase = A + (size_t)(mt * 128) * 256;
    const uint32_t* Bbase = Bp + (size_t)nt * 8 * 2048;

    // ldmatrix per-lane constants: row within 64-row warp tile
    const int rbase = wm + (lane & 15);
    const int uoff  = lane >> 4;       // 0/1: k-unit select
    const int s3    = rbase & 3;       // swizzle term (invariant under +16 rows)

    auto issue = [&](int st) {
        const int slot = st % 3;
        const uint32_t smA = smb + slot * 16384;
        const uint32_t smB = smA + 8192;
        const int k0 = st * 32;
        // A: 512 16B units; unit idx -> m = idx>>2, u = idx&3; phys = u ^ (m&3)
#pragma unroll
        for (int i = 0; i < 2; i++) {
            const int idx = tid + i * 256;
            const int m = idx >> 2, u = idx & 3;
            cp_async16(smA + m * 64 + ((u ^ (m & 3)) * 16),
                       Abase + (size_t)m * 256 + k0 + u * 8);
        }
        // B: straight copy of the pre-packed stage image
        const char* bsrc = (const char*)(Bbase + (size_t)st * 2048);
#pragma unroll
        for (int i = 0; i < 2; i++) {
            const int idx = tid + i * 256;
            cp_async16(smB + idx * 16, bsrc + (size_t)idx * 16);
        }
        CP_COMMIT();
    };

    issue(0);
    issue(1);

    float acc[4][4][4] = {};

#pragma unroll 1
    for (int st = 0; st < 8; st++) {
        if (st + 2 < 8) issue(st + 2);
        if (st < 6)       asm volatile("cp.async.wait_group 2;" ::: "memory");
        else if (st == 6) asm volatile("cp.async.wait_group 1;" ::: "memory");
        else              asm volatile("cp.async.wait_group 0;" ::: "memory");
        __syncthreads();

        const int slot = st % 3;
        const uint32_t smA = smb + slot * 16384;
        const uint32_t smB = smA + 8192;

#pragma unroll
        for (int tk = 0; tk < 2; tk++) {
            unsigned af[4][4];
            const uint32_t uphys = (uint32_t)((tk * 2 + uoff) ^ s3) * 16;
#pragma unroll
            for (int tm = 0; tm < 4; tm++)
                LDSM_X4(af[tm], smA + (uint32_t)(rbase + tm * 16) * 64 + uphys);

            unsigned bf[4][2];
#pragma unroll
            for (int tn = 0; tn < 4; tn++) {
                const int widx = (((wn >> 3) + tn) * 2 + tk) * 32 + lane;
                asm("ld.shared.v2.b32 {%0,%1}, [%2];"
                    : "=r"(bf[tn][0]), "=r"(bf[tn][1]) : "r"(smB + widx * 8));
            }
#pragma unroll
            for (int mi = 0; mi < 4; mi++)
#pragma unroll
                for (int ni = 0; ni < 4; ni++)
                    mma_f16(acc[mi][ni], af[mi], bf[ni]);
        }
        __syncthreads();
    }

    // epilogue: bias add + float2 stores
#pragma unroll
    for (int mi = 0; mi < 4; mi++) {
        const int r = mt * 128 + wm + mi * 16 + (lane >> 2);
#pragma unroll
        for (int ni = 0; ni < 4; ni++) {
            const int c = nt * 128 + wn + ni * 8 + (lane & 3) * 2;
            const float2 bv = *(const float2*)&bias[c];
            float2 o0, o1;
            o0.x = acc[mi][ni][0] + bv.x;
            o0.y = acc[mi][ni][1] + bv.y;
            o1.x = acc[mi][ni][2] + bv.x;
            o1.y = acc[mi][ni][3] + bv.y;
            *(float2*)&C[(size_t)r * N + c]       = o0;
            *(float2*)&C[(size_t)(r + 8) * N + c] = o1;
        }
    }
}

// ---------------------------------------------------------------------------
// Deformable sampling — warp-autonomous; output stored as fp16 (g_accH).
// ---------------------------------------------------------------------------
__global__ __launch_bounds__(256) void ms_sample_kernel(
    const float* __restrict__ refp)   // [B, Lq, 4, 2]
{
    const int q  = blockIdx.x;
    const int b  = blockIdx.y;
    const int bq = b * LQ + q;
    const int t  = threadIdx.x;
    const int h  = t >> 5;
    const int lid = t & 31;

    __shared__ int2 s_tap[NH][64];

    {
        const int lp = lid;
        const float* ap = g_offattn + (size_t)bq * NFUSE + 256 + h * 16;
        float logit = (lid < 16) ? ap[lp] : -1e30f;
        float m = logit;
#pragma unroll
        for (int o = 8; o; o >>= 1) m = fmaxf(m, __shfl_xor_sync(0xFFFFFFFFu, m, o));
        float e = (lid < 16) ? __expf(logit - m) : 0.0f;
        float ssum = e;
#pragma unroll
        for (int o = 8; o; o >>= 1) ssum += __shfl_xor_sync(0xFFFFFFFFu, ssum, o);

        if (lid < 16) {
            const float aw = e / ssum;
            const int l = lp >> 2;
            const int W = 64 >> l;
            const int start = (l == 0) ? 0 : (l == 1) ? 4096 : (l == 2) ? 5120 : 5376;

            const float rx = refp[((size_t)bq * 4 + l) * 2 + 0];
            const float ry = refp[((size_t)bq * 4 + l) * 2 + 1];
            const float* op = g_offattn + (size_t)bq * NFUSE + h * 32 + lp * 2;

            const float x = fmaf(rx, (float)W, op[0]) - 0.5f;
            const float y = fmaf(ry, (float)W, op[1]) - 0.5f;
            const float x0f = floorf(x), y0f = floorf(y);
            const int x0 = (int)x0f, y0 = (int)y0f;
            const float wx = x - x0f, wy = y - y0f;

            const bool xi0 = (x0 >= 0) && (x0 < W);
            const bool xi1 = (x0 + 1 >= 0) && (x0 + 1 < W);
            const bool yi0 = (y0 >= 0) && (y0 < W);
            const bool yi1 = (y0 + 1 >= 0) && (y0 + 1 < W);

            const int i00 = start + y0 * W + x0;
            int2* tp = &s_tap[h][lp * 4];
            bool v;
            v = xi0 && yi0;
            tp[0] = make_int2(v ? i00 : 0,         __float_as_int(v ? aw * (1.f - wx) * (1.f - wy) : 0.f));
            v = xi1 && yi0;
            tp[1] = make_int2(v ? i00 + 1 : 0,     __float_as_int(v ? aw * wx * (1.f - wy) : 0.f));
            v = xi0 && yi1;
            tp[2] = make_int2(v ? i00 + W : 0,     __float_as_int(v ? aw * (1.f - wx) * wy : 0.f));
            v = xi1 && yi1;
            tp[3] = make_int2(v ? i00 + W + 1 : 0, __float_as_int(v ? aw * wx * wy : 0.f));
        }
    }
    __syncwarp();

    const int sub = lid >> 3;
    const int c4  = (lid & 7) * 4;
    const float* vb4 = g_vproj + (size_t)b * LV * CD + h * HD + c4;
    const int2* taps = &s_tap[h][0];

    float ax = 0.f, ay = 0.f, az = 0.f, aw_ = 0.f;
#pragma unroll
    for (int j = 0; j < 16; j++) {
        const int2 tv = taps[j * 4 + sub];
        const float w = __int_as_float(tv.y);
        const float4 v = *(const float4*)(vb4 + (size_t)tv.x * CD);
        ax  = fmaf(w, v.x, ax);
        ay  = fmaf(w, v.y, ay);
        az  = fmaf(w, v.z, az);
        aw_ = fmaf(w, v.w, aw_);
    }
#pragma unroll
    for (int o = 8; o <= 16; o <<= 1) {
        ax  += __shfl_xor_sync(0xFFFFFFFFu, ax,  o);
        ay  += __shfl_xor_sync(0xFFFFFFFFu, ay,  o);
        az  += __shfl_xor_sync(0xFFFFFFFFu, az,  o);
        aw_ += __shfl_xor_sync(0xFFFFFFFFu, aw_, o);
    }
    if (lid < 8) {
        __half2 h0 = __floats2half2_rn(ax, ay);
        __half2 h1 = __floats2half2_rn(az, aw_);
        uint2 o;
        o.x = *(uint32_t*)&h0;
        o.y = *(uint32_t*)&h1;
        *(uint2*)&g_accH[(size_t)bq * CD + h * HD + lid * 4] = o;
    }
}

// ---------------------------------------------------------------------------
// kernel_launch
// Inputs: query, reference_points, value, W_off, b_off, W_attn, b_attn,
//         W_val, b_val, W_out, b_out
// ---------------------------------------------------------------------------
extern "C" void kernel_launch(void* const* d_in, const int* in_sizes, int n_in,
                              void* d_out, int out_size)
{
    const float* query = (const float*)d_in[0];
    const float* refp  = (const float*)d_in[1];
    const float* value = (const float*)d_in[2];
    const float* W_off = (const float*)d_in[3];
    const float* b_off = (const float*)d_in[4];
    const float* W_at  = (const float*)d_in[5];
    const float* b_at  = (const float*)d_in[6];
    const float* W_val = (const float*)d_in[7];
    const float* b_val = (const float*)d_in[8];
    const float* W_out = (const float*)d_in[9];
    const float* b_out = (const float*)d_in[10];
    float* out = (float*)d_out;

    float *vproj, *offattn, *bf;
    __half *qh, *vh, *acch;
    uint32_t *bpv, *bpf, *bpo;
    cudaGetSymbolAddress((void**)&vproj,   g_vproj);
    cudaGetSymbolAddress((void**)&offattn, g_offattn);
    cudaGetSymbolAddress((void**)&qh,      g_qH);
    cudaGetSymbolAddress((void**)&vh,      g_vH);
    cudaGetSymbolAddress((void**)&acch,    g_accH);
    cudaGetSymbolAddress((void**)&bf,      g_bf);
    cudaGetSymbolAddress((void**)&bpv,     g_BpV);
    cudaGetSymbolAddress((void**)&bpf,     g_BpF);
    cudaGetSymbolAddress((void**)&bpo,     g_BpO);

    dim3 blk(256);

    convert_h<<<2 * MROWS * 64 / 256, blk>>>((const float4*)query, (const float4*)value);
    pack_B<<<448, blk>>>(W_off, b_off, W_at, b_at, W_val, W_out);
    // fused: V-proj (2 n-tiles) + offattn-proj (3 n-tiles)
    gemm_f16<<<dim3(5, MTILES), blk>>>(vh, bpv, b_val, vproj, 256, 2,
                                       qh, bpf, bf, offattn, NFUSE);
    ms_sample_kernel<<<dim3(LQ, NB), blk>>>(refp);
    gemm_f16<<<dim3(2, MTILES), blk>>>(acch, bpo, b_out, out, 256, 2,
                                       acch, bpo, b_out, out, 256);
}